// round 9
// baseline (speedup 1.0000x reference)
#include <cuda_runtime.h>
#include <math.h>

#define NB 32
#define NK 4
#define NC 256
#define HW 1024
#define MID 32
#define KC 1280   // (K+1)*C
#define EPSV 1e-5f

#define NBLK 148          // one block per SM, all resident (required for barrier)
#define NROW_TOT 8192     // b*c rows
#define MAXROWS 56        // ceil(8192/148)
#define SROWS 10          // rows stashed in smem per block
#define STASKS (SROWS*5)  // tensor-rows stashed (50 * 4KB = 200KB)

// Scratch (device globals — no allocation allowed). Barrier counters return
// to 0 every launch (graph-replay safe, proven in rounds 5-8).
__device__ float g_feats[NB * KC];
__device__ unsigned g_cnt1;
__device__ unsigned g_cnt2;

// ---------------------------------------------------------------------------
// Fused persistent kernel, 148 blocks x 1024 threads:
//   Phase 1: means for this block's ~55 rows x 5 tensors (warp per tensor-row).
//            First STASKS tensor-rows are stashed in dynamic smem and loaded
//            with .cs (evict-first) since they won't be needed from L2 again.
//   Global barrier (self-resetting counters).
//   Gates:   h[b] + sigmoid/softmax for this block's rows (<=2 distinct b).
//   Phase 2: gated sum. Stashed rows come from smem; the rest are re-read in
//            REVERSE order with .cs loads (no L2 pollution on miss) so the
//            tail of phase 1's stream hits in L2. Output stored with .cs.
// ---------------------------------------------------------------------------
extern __shared__ float4 stash4[];   // STASKS * 256 float4 = 204800 B

__global__ __launch_bounds__(1024, 1) void fused_kernel(
    const float* __restrict__ y,
    const float* __restrict__ x0,
    const float* __restrict__ x1,
    const float* __restrict__ x2,
    const float* __restrict__ x3,
    const float* __restrict__ conv1_w,   // [MID, KC]
    const float* __restrict__ bn_gamma,
    const float* __restrict__ bn_beta,
    const float* __restrict__ bn_mean,
    const float* __restrict__ bn_var,
    const float* __restrict__ conv2_w,   // [KC, MID]
    const float* __restrict__ conv2_b,   // [KC]
    float* __restrict__ out)
{
    __shared__ float h_s[MID];
    __shared__ float sw1[MAXROWS];
    __shared__ float sw2[NK][MAXROWS];

    const int tid  = threadIdx.x;
    const int warp = tid >> 5;
    const int lane = tid & 31;

    const int start = (int)(((long)blockIdx.x * NROW_TOT) / NBLK);
    const int end   = (int)(((long)(blockIdx.x + 1) * NROW_TOT) / NBLK);
    const int nrows = end - start;          // 55 or 56

    // ---------------- Phase 1: means (warp per tensor-row) ----------------
    {
        const int ntasks = nrows * 5;
        for (int task = warp; task < ntasks; task += 32) {
            int rel = task / 5;
            int t   = task - rel * 5;
            int bc  = start + rel;
            const float* src = (t == 0) ? y : (t == 1) ? x0 : (t == 2) ? x1
                             : (t == 3) ? x2 : x3;
            const float4* p = (const float4*)(src + (size_t)bc * HW);
            float sum = 0.f;
            if (task < STASKS) {
                float4* st = stash4 + task * 256;
#pragma unroll
                for (int i = 0; i < 8; i++) {
                    float4 v = __ldcs(p + lane + i * 32);   // evict-first
                    st[lane + i * 32] = v;
                    sum += (v.x + v.y) + (v.z + v.w);
                }
            } else {
#pragma unroll
                for (int i = 0; i < 8; i++) {
                    float4 v = p[lane + i * 32];            // keep in L2
                    sum += (v.x + v.y) + (v.z + v.w);
                }
            }
#pragma unroll
            for (int o = 16; o; o >>= 1) sum += __shfl_xor_sync(0xFFFFFFFFu, sum, o);
            if (lane == 0) {
                int b = bc >> 8, c = bc & 255;
                g_feats[b * KC + t * NC + c] = sum * (1.0f / 1024.0f);
            }
        }
    }

    // ---------------- Grid barrier (self-resetting, replay-safe) ----------
    __threadfence();
    __syncthreads();
    if (tid == 0) {
        atomicAdd(&g_cnt1, 1u);
        while (*((volatile unsigned*)&g_cnt1) < (unsigned)NBLK) { }
        __threadfence();
        unsigned old = atomicAdd(&g_cnt2, 1u);
        if (old == (unsigned)(NBLK - 1)) {
            g_cnt1 = 0u;
            __threadfence();
            g_cnt2 = 0u;
        }
    }
    __syncthreads();

    // ---------------- Gates for this block's rows (<=2 distinct b) ---------
    {
        const int b0 = start >> 8;
        const int b1 = (start + nrows - 1) >> 8;
        for (int bb = b0; bb <= b1; bb++) {
            // Warp m: h[m] = relu(BN(feats[bb,:] . conv1_w[m,:]))
            {
                const float4* f4 = (const float4*)(g_feats + bb * KC);  // 320 f4
                const float4* w4 = (const float4*)(conv1_w + warp * KC);
                float acc = 0.f;
#pragma unroll
                for (int i = 0; i < 10; i++) {
                    float4 fv = f4[lane + i * 32];
                    float4 wv = w4[lane + i * 32];
                    acc += fv.x * wv.x + fv.y * wv.y + fv.z * wv.z + fv.w * wv.w;
                }
#pragma unroll
                for (int o = 16; o; o >>= 1) acc += __shfl_xor_sync(0xFFFFFFFFu, acc, o);
                if (lane == 0) {
                    float inv = rsqrtf(bn_var[warp] + EPSV);
                    float hv  = (acc - bn_mean[warp]) * (bn_gamma[warp] * inv) + bn_beta[warp];
                    h_s[warp] = fmaxf(hv, 0.f);
                }
            }
            __syncthreads();

            if (tid < nrows) {
                int bc = start + tid;
                if ((bc >> 8) == bb) {
                    int c = bc & 255;
                    float h[MID];
#pragma unroll
                    for (int m = 0; m < MID; m++) h[m] = h_s[m];

                    float wv[5];
#pragma unroll
                    for (int t = 0; t < 5; t++) {
                        int j = t * NC + c;
                        const float4* w2r = (const float4*)(conv2_w + j * MID);
                        float acc = conv2_b[j];
#pragma unroll
                        for (int q = 0; q < 8; q++) {
                            float4 v = w2r[q];
                            acc = fmaf(h[q * 4 + 0], v.x, acc);
                            acc = fmaf(h[q * 4 + 1], v.y, acc);
                            acc = fmaf(h[q * 4 + 2], v.z, acc);
                            acc = fmaf(h[q * 4 + 3], v.w, acc);
                        }
                        wv[t] = acc;
                    }

                    sw1[tid] = 1.0f / (1.0f + expf(-wv[0]));
                    float mx = fmaxf(fmaxf(wv[1], wv[2]), fmaxf(wv[3], wv[4]));
                    float e0 = expf(wv[1] - mx);
                    float e1 = expf(wv[2] - mx);
                    float e2 = expf(wv[3] - mx);
                    float e3 = expf(wv[4] - mx);
                    float inv = 1.0f / (e0 + e1 + e2 + e3);
                    sw2[0][tid] = e0 * inv;
                    sw2[1][tid] = e1 * inv;
                    sw2[2][tid] = e2 * inv;
                    sw2[3][tid] = e3 * inv;
                }
            }
            __syncthreads();
        }
    }

    // ---------------- Phase 2: gated sum, reverse order --------------------
    {
        const int g = tid >> 8;          // 0..3 (row group)
        const int r = tid & 255;         // float4 index within the row
        for (int it = ((nrows + 3) >> 2) - 1; it >= 0; it--) {
            int rel = it * 4 + g;
            if (rel >= nrows) continue;
            int bc = start + rel;

            float w1 = sw1[rel];
            float wa = sw2[0][rel];
            float wb = sw2[1][rel];
            float wc = sw2[2][rel];
            float wd = sw2[3][rel];

            float4 vy, va, vb, vc, vd;
            if (rel < SROWS) {
                const float4* st = stash4 + rel * 5 * 256;
                vy = st[0 * 256 + r];
                va = st[1 * 256 + r];
                vb = st[2 * 256 + r];
                vc = st[3 * 256 + r];
                vd = st[4 * 256 + r];
            } else {
                size_t base = (size_t)bc * HW;
                vy = __ldcs((const float4*)(y  + base) + r);
                va = __ldcs((const float4*)(x0 + base) + r);
                vb = __ldcs((const float4*)(x1 + base) + r);
                vc = __ldcs((const float4*)(x2 + base) + r);
                vd = __ldcs((const float4*)(x3 + base) + r);
            }

            float4 res;
            res.x = fmaf(vy.x, w1, fmaf(va.x, wa, fmaf(vb.x, wb, fmaf(vc.x, wc, vd.x * wd))));
            res.y = fmaf(vy.y, w1, fmaf(va.y, wa, fmaf(vb.y, wb, fmaf(vc.y, wc, vd.y * wd))));
            res.z = fmaf(vy.z, w1, fmaf(va.z, wa, fmaf(vb.z, wb, fmaf(vc.z, wc, vd.z * wd))));
            res.w = fmaf(vy.w, w1, fmaf(va.w, wa, fmaf(vc.z, 0.f, vd.w * wd)));  // placeholder fixed below
            res.w = fmaf(vy.w, w1, fmaf(va.w, wa, fmaf(vb.w, wb, fmaf(vc.w, wc, vd.w * wd))));
            __stcs((float4*)(out + (size_t)bc * HW) + r, res);
        }
    }
}

extern "C" void kernel_launch(void* const* d_in, const int* in_sizes, int n_in,
                              void* d_out, int out_size)
{
    const float* y       = (const float*)d_in[0];
    const float* x0      = (const float*)d_in[1];
    const float* x1      = (const float*)d_in[2];
    const float* x2      = (const float*)d_in[3];
    const float* x3      = (const float*)d_in[4];
    const float* conv1_w = (const float*)d_in[5];
    const float* bn_g    = (const float*)d_in[6];
    const float* bn_b    = (const float*)d_in[7];
    const float* bn_m    = (const float*)d_in[8];
    const float* bn_v    = (const float*)d_in[9];
    const float* conv2_w = (const float*)d_in[10];
    const float* conv2_b = (const float*)d_in[11];
    float* out = (float*)d_out;

    const int dyn_smem = STASKS * 256 * sizeof(float4);   // 204800 B
    cudaFuncSetAttribute(fused_kernel,
                         cudaFuncAttributeMaxDynamicSharedMemorySize, dyn_smem);

    fused_kernel<<<NBLK, 1024, dyn_smem>>>(y, x0, x1, x2, x3,
                                           conv1_w, bn_g, bn_b, bn_m, bn_v,
                                           conv2_w, conv2_b, out);
}

// round 10
// speedup vs baseline: 1.1440x; 1.1440x over previous
#include <cuda_runtime.h>
#include <math.h>

#define NB 32
#define NK 4
#define NC 256
#define HW 1024
#define MID 32
#define KC 1280   // (K+1)*C
#define EPSV 1e-5f

#define NBLK 128        // 8192 rows / 64 per block (round-8 proven layout)
#define BC_PER_BLK 64
#define SROWS 10        // rows stashed in smem per block
#define STASKS (SROWS*5)  // 50 tensor-rows * 4KB = 200KB dynamic smem

// Scratch (device globals — no allocation allowed). Barrier counters return
// to 0 every launch (graph-replay safe, proven rounds 5-8).
__device__ float g_feats[NB * KC];
__device__ unsigned g_cnt1;
__device__ unsigned g_cnt2;

extern __shared__ float4 stash4[];   // STASKS * 256 float4 = 204800 B

// ---------------------------------------------------------------------------
// Fused persistent kernel, 128 blocks x 1024 threads. ALL loop trip counts
// are compile-time (round-9 lesson: runtime bounds kill unroll -> MLP -> BW).
//   Phase 1: means, warp per tensor-row, 10 static iterations. First 50
//            tensor-rows stashed to smem via .cs loads (evict-first: they
//            are never needed from L2 again).
//   Grid barrier (self-resetting).
//   Gates:   h[b] + sigmoid/softmax (one b per block since 64 | 256).
//   Phase 2: gated sum, 16 static iterations in REVERSE order (tail of
//            phase-1 stream is L2-resident). Stashed rows from smem; misses
//            via .cs; stores via .cs — neither pollutes L2.
// ---------------------------------------------------------------------------
__global__ __launch_bounds__(1024, 1) void fused_kernel(
    const float* __restrict__ y,
    const float* __restrict__ x0,
    const float* __restrict__ x1,
    const float* __restrict__ x2,
    const float* __restrict__ x3,
    const float* __restrict__ conv1_w,   // [MID, KC]
    const float* __restrict__ bn_gamma,
    const float* __restrict__ bn_beta,
    const float* __restrict__ bn_mean,
    const float* __restrict__ bn_var,
    const float* __restrict__ conv2_w,   // [KC, MID]
    const float* __restrict__ conv2_b,   // [KC]
    float* __restrict__ out)
{
    __shared__ float h_s[MID];
    __shared__ float sw1[BC_PER_BLK];
    __shared__ float sw2[NK][BC_PER_BLK];

    const int tid  = threadIdx.x;
    const int warp = tid >> 5;
    const int lane = tid & 31;
    const int s    = blockIdx.x * BC_PER_BLK;   // first bc row of this block
    const int b    = s >> 8;                    // single b per block (64 | 256)

    // ---------------- Phase 1: means (warp per tensor-row) ----------------
#pragma unroll
    for (int it = 0; it < 10; it++) {
        int task = warp + it * 32;              // 0..319
        int rel  = task / 5;
        int t    = task - rel * 5;
        int bc   = s + rel;
        const float* src = (t == 0) ? y : (t == 1) ? x0 : (t == 2) ? x1
                         : (t == 3) ? x2 : x3;
        const float4* p = (const float4*)(src + (size_t)bc * HW);
        float sum = 0.f;
        if (task < STASKS) {
            float4* st = stash4 + task * 256;
#pragma unroll
            for (int i = 0; i < 8; i++) {
                float4 v = __ldcs(p + lane + i * 32);   // evict-first
                st[lane + i * 32] = v;
                sum += (v.x + v.y) + (v.z + v.w);
            }
        } else {
#pragma unroll
            for (int i = 0; i < 8; i++) {
                float4 v = p[lane + i * 32];            // keep in L2
                sum += (v.x + v.y) + (v.z + v.w);
            }
        }
#pragma unroll
        for (int o = 16; o; o >>= 1) sum += __shfl_xor_sync(0xFFFFFFFFu, sum, o);
        if (lane == 0) {
            int c = bc & 255;
            g_feats[b * KC + t * NC + c] = sum * (1.0f / 1024.0f);
        }
    }

    // ---------------- Grid barrier (self-resetting, replay-safe) ----------
    __threadfence();
    __syncthreads();
    if (tid == 0) {
        atomicAdd(&g_cnt1, 1u);
        while (*((volatile unsigned*)&g_cnt1) < (unsigned)NBLK) { }
        __threadfence();
        unsigned old = atomicAdd(&g_cnt2, 1u);
        if (old == (unsigned)(NBLK - 1)) {
            g_cnt1 = 0u;
            __threadfence();
            g_cnt2 = 0u;
        }
    }
    __syncthreads();

    // ---------------- Gates: h[b][:] then per-channel gates ----------------
    {
        int m = warp;
        const float4* f4 = (const float4*)(g_feats + b * KC);   // 320 float4
        const float4* w4 = (const float4*)(conv1_w + m * KC);
        float acc = 0.f;
#pragma unroll
        for (int i = 0; i < 10; i++) {
            float4 fv = f4[lane + i * 32];
            float4 wv = w4[lane + i * 32];
            acc += fv.x * wv.x + fv.y * wv.y + fv.z * wv.z + fv.w * wv.w;
        }
#pragma unroll
        for (int o = 16; o; o >>= 1) acc += __shfl_xor_sync(0xFFFFFFFFu, acc, o);
        if (lane == 0) {
            float inv = rsqrtf(bn_var[m] + EPSV);
            float hv  = (acc - bn_mean[m]) * (bn_gamma[m] * inv) + bn_beta[m];
            h_s[m] = fmaxf(hv, 0.f);
        }
    }
    __syncthreads();

    if (tid < BC_PER_BLK) {
        int bc = s + tid;
        int c  = bc & 255;
        float h[MID];
#pragma unroll
        for (int m = 0; m < MID; m++) h[m] = h_s[m];

        float wv[5];
#pragma unroll
        for (int t = 0; t < 5; t++) {
            int j = t * NC + c;
            const float4* w2r = (const float4*)(conv2_w + j * MID);
            float acc = conv2_b[j];
#pragma unroll
            for (int q = 0; q < 8; q++) {
                float4 v = w2r[q];
                acc = fmaf(h[q * 4 + 0], v.x, acc);
                acc = fmaf(h[q * 4 + 1], v.y, acc);
                acc = fmaf(h[q * 4 + 2], v.z, acc);
                acc = fmaf(h[q * 4 + 3], v.w, acc);
            }
            wv[t] = acc;
        }

        sw1[tid] = 1.0f / (1.0f + expf(-wv[0]));
        float mx = fmaxf(fmaxf(wv[1], wv[2]), fmaxf(wv[3], wv[4]));
        float e0 = expf(wv[1] - mx);
        float e1 = expf(wv[2] - mx);
        float e2 = expf(wv[3] - mx);
        float e3 = expf(wv[4] - mx);
        float inv = 1.0f / (e0 + e1 + e2 + e3);
        sw2[0][tid] = e0 * inv;
        sw2[1][tid] = e1 * inv;
        sw2[2][tid] = e2 * inv;
        sw2[3][tid] = e3 * inv;
    }
    __syncthreads();

    // ---------------- Phase 2: gated sum, REVERSE order --------------------
    {
        const int g = tid >> 8;          // 0..3 (row group)
        const int r = tid & 255;         // float4 index within the 1024-row
#pragma unroll
        for (int it = (BC_PER_BLK / 4) - 1; it >= 0; it--) {
            int rel = it * 4 + g;
            int bc  = s + rel;

            float w1 = sw1[rel];
            float wa = sw2[0][rel];
            float wb = sw2[1][rel];
            float wc = sw2[2][rel];
            float wd = sw2[3][rel];

            float4 vy, va, vb, vc, vd;
            if (rel < SROWS) {
                const float4* st = stash4 + rel * 5 * 256;
                vy = st[0 * 256 + r];
                va = st[1 * 256 + r];
                vb = st[2 * 256 + r];
                vc = st[3 * 256 + r];
                vd = st[4 * 256 + r];
            } else {
                size_t base = (size_t)bc * HW;
                vy = __ldcs((const float4*)(y  + base) + r);
                va = __ldcs((const float4*)(x0 + base) + r);
                vb = __ldcs((const float4*)(x1 + base) + r);
                vc = __ldcs((const float4*)(x2 + base) + r);
                vd = __ldcs((const float4*)(x3 + base) + r);
            }

            float4 res;
            res.x = fmaf(vy.x, w1, fmaf(va.x, wa, fmaf(vb.x, wb, fmaf(vc.x, wc, vd.x * wd))));
            res.y = fmaf(vy.y, w1, fmaf(va.y, wa, fmaf(vb.y, wb, fmaf(vc.y, wc, vd.y * wd))));
            res.z = fmaf(vy.z, w1, fmaf(va.z, wa, fmaf(vb.z, wb, fmaf(vc.z, wc, vd.z * wd))));
            res.w = fmaf(vy.w, w1, fmaf(va.w, wa, fmaf(vb.w, wb, fmaf(vc.w, wc, vd.w * wd))));
            __stcs((float4*)(out + (size_t)bc * HW) + r, res);
        }
    }
}

extern "C" void kernel_launch(void* const* d_in, const int* in_sizes, int n_in,
                              void* d_out, int out_size)
{
    const float* y       = (const float*)d_in[0];
    const float* x0      = (const float*)d_in[1];
    const float* x1      = (const float*)d_in[2];
    const float* x2      = (const float*)d_in[3];
    const float* x3      = (const float*)d_in[4];
    const float* conv1_w = (const float*)d_in[5];
    const float* bn_g    = (const float*)d_in[6];
    const float* bn_b    = (const float*)d_in[7];
    const float* bn_m    = (const float*)d_in[8];
    const float* bn_v    = (const float*)d_in[9];
    const float* conv2_w = (const float*)d_in[10];
    const float* conv2_b = (const float*)d_in[11];
    float* out = (float*)d_out;

    const int dyn_smem = STASKS * 256 * sizeof(float4);   // 204800 B
    cudaFuncSetAttribute(fused_kernel,
                         cudaFuncAttributeMaxDynamicSharedMemorySize, dyn_smem);

    fused_kernel<<<NBLK, 1024, dyn_smem>>>(y, x0, x1, x2, x3,
                                           conv1_w, bn_g, bn_b, bn_m, bn_v,
                                           conv2_w, conv2_b, out);
}

// round 12
// speedup vs baseline: 1.4160x; 1.2377x over previous
#include <cuda_runtime.h>
#include <math.h>

#define NB 32
#define NK 4
#define NC 256
#define HW 1024
#define MID 32
#define KC 1280   // (K+1)*C
#define EPSV 1e-5f

#define NBLK 128        // 8192 rows / 64 per block (round-8 proven layout)
#define BC_PER_BLK 64
#define SROWS 8         // rows stashed in smem per block (multiple of 4!)
#define STASKS (SROWS*5)  // 40 tensor-rows * 4KB = 160KB dynamic smem

// Scratch (device globals — no allocation allowed). Barrier counters return
// to 0 every launch (graph-replay safe, proven rounds 5-10).
__device__ float g_feats[NB * KC];
__device__ unsigned g_cnt1;
__device__ unsigned g_cnt2;

extern __shared__ float4 stash4[];   // STASKS * 256 float4 = 163840 B

// ---------------------------------------------------------------------------
// Fused persistent kernel, 128 blocks x 1024 threads.
// Round-10 lesson: stash predicates must be warp-uniform + loop-invariant
// (phase 1) or compile-time (phase 2), or MLP batching and I$ collapse.
//   Phase 1: warp w owns rows 2w, 2w+1 (x5 tensors, static loops). Warps 0-3
//            stash rows 0-7 to smem via .cs (those bytes never need L2).
//   Grid barrier (self-resetting).
//   Gates:   h[b] + sigmoid/softmax (one b per block since 64 | 256).
//   Phase 2: identical load path to round 8 (plain loads, .cs stores),
//            REVERSE order; iterations it<2 (rows 0-7) read smem — branch
//            on compile-time `it` only.
// ---------------------------------------------------------------------------
__global__ __launch_bounds__(1024, 1) void fused_kernel(
    const float* __restrict__ y,
    const float* __restrict__ x0,
    const float* __restrict__ x1,
    const float* __restrict__ x2,
    const float* __restrict__ x3,
    const float* __restrict__ conv1_w,   // [MID, KC]
    const float* __restrict__ bn_gamma,
    const float* __restrict__ bn_beta,
    const float* __restrict__ bn_mean,
    const float* __restrict__ bn_var,
    const float* __restrict__ conv2_w,   // [KC, MID]
    const float* __restrict__ conv2_b,   // [KC]
    float* __restrict__ out)
{
    __shared__ float h_s[MID];
    __shared__ float sw1[BC_PER_BLK];
    __shared__ float sw2[NK][BC_PER_BLK];

    const int tid  = threadIdx.x;
    const int warp = tid >> 5;
    const int lane = tid & 31;
    const int s    = blockIdx.x * BC_PER_BLK;   // first bc row of this block
    const int b    = s >> 8;                    // single b per block (64 | 256)

    // ---------------- Phase 1: means (warp owns 2 rows x 5 tensors) --------
    {
        const float* srcs[5] = { y, x0, x1, x2, x3 };
        if (warp < SROWS / 2) {
            // Stash path: rows 2w, 2w+1 < 8. Loop-invariant branch; bodies
            // fully static -> batched LDG.CS + STS.
#pragma unroll
            for (int rr = 0; rr < 2; rr++) {
                int rel = warp * 2 + rr;
                int bc  = s + rel;
#pragma unroll
                for (int t = 0; t < 5; t++) {
                    const float4* p = (const float4*)(srcs[t] + (size_t)bc * HW);
                    float4* st = stash4 + (rel * 5 + t) * 256;
                    float sum = 0.f;
#pragma unroll
                    for (int i = 0; i < 8; i++) {
                        float4 v = __ldcs(p + lane + i * 32);  // evict-first
                        st[lane + i * 32] = v;
                        sum += (v.x + v.y) + (v.z + v.w);
                    }
#pragma unroll
                    for (int o = 16; o; o >>= 1)
                        sum += __shfl_xor_sync(0xFFFFFFFFu, sum, o);
                    if (lane == 0)
                        g_feats[b * KC + t * NC + (bc & 255)] = sum * (1.0f / 1024.0f);
                }
            }
        } else {
            // Normal path: rows 8..63, keep in L2 for the phase-2 re-read.
#pragma unroll
            for (int rr = 0; rr < 2; rr++) {
                int rel = warp * 2 + rr;
                int bc  = s + rel;
#pragma unroll
                for (int t = 0; t < 5; t++) {
                    const float4* p = (const float4*)(srcs[t] + (size_t)bc * HW);
                    float sum = 0.f;
#pragma unroll
                    for (int i = 0; i < 8; i++) {
                        float4 v = p[lane + i * 32];
                        sum += (v.x + v.y) + (v.z + v.w);
                    }
#pragma unroll
                    for (int o = 16; o; o >>= 1)
                        sum += __shfl_xor_sync(0xFFFFFFFFu, sum, o);
                    if (lane == 0)
                        g_feats[b * KC + t * NC + (bc & 255)] = sum * (1.0f / 1024.0f);
                }
            }
        }
    }

    // ---------------- Grid barrier (self-resetting, replay-safe) ----------
    __threadfence();
    __syncthreads();
    if (tid == 0) {
        atomicAdd(&g_cnt1, 1u);
        while (*((volatile unsigned*)&g_cnt1) < (unsigned)NBLK) { }
        __threadfence();
        unsigned old = atomicAdd(&g_cnt2, 1u);
        if (old == (unsigned)(NBLK - 1)) {
            g_cnt1 = 0u;
            __threadfence();
            g_cnt2 = 0u;
        }
    }
    __syncthreads();

    // ---------------- Gates: h[b][:] then per-channel gates ----------------
    {
        int m = warp;
        const float4* f4 = (const float4*)(g_feats + b * KC);   // 320 float4
        const float4* w4 = (const float4*)(conv1_w + m * KC);
        float acc = 0.f;
#pragma unroll
        for (int i = 0; i < 10; i++) {
            float4 fv = f4[lane + i * 32];
            float4 wv = w4[lane + i * 32];
            acc += fv.x * wv.x + fv.y * wv.y + fv.z * wv.z + fv.w * wv.w;
        }
#pragma unroll
        for (int o = 16; o; o >>= 1) acc += __shfl_xor_sync(0xFFFFFFFFu, acc, o);
        if (lane == 0) {
            float inv = rsqrtf(bn_var[m] + EPSV);
            float hv  = (acc - bn_mean[m]) * (bn_gamma[m] * inv) + bn_beta[m];
            h_s[m] = fmaxf(hv, 0.f);
        }
    }
    __syncthreads();

    if (tid < BC_PER_BLK) {
        int bc = s + tid;
        int c  = bc & 255;
        float h[MID];
#pragma unroll
        for (int m = 0; m < MID; m++) h[m] = h_s[m];

        float wv[5];
#pragma unroll
        for (int t = 0; t < 5; t++) {
            int j = t * NC + c;
            const float4* w2r = (const float4*)(conv2_w + j * MID);
            float acc = conv2_b[j];
#pragma unroll
            for (int q = 0; q < 8; q++) {
                float4 v = w2r[q];
                acc = fmaf(h[q * 4 + 0], v.x, acc);
                acc = fmaf(h[q * 4 + 1], v.y, acc);
                acc = fmaf(h[q * 4 + 2], v.z, acc);
                acc = fmaf(h[q * 4 + 3], v.w, acc);
            }
            wv[t] = acc;
        }

        sw1[tid] = 1.0f / (1.0f + expf(-wv[0]));
        float mx = fmaxf(fmaxf(wv[1], wv[2]), fmaxf(wv[3], wv[4]));
        float e0 = expf(wv[1] - mx);
        float e1 = expf(wv[2] - mx);
        float e2 = expf(wv[3] - mx);
        float e3 = expf(wv[4] - mx);
        float inv = 1.0f / (e0 + e1 + e2 + e3);
        sw2[0][tid] = e0 * inv;
        sw2[1][tid] = e1 * inv;
        sw2[2][tid] = e2 * inv;
        sw2[3][tid] = e3 * inv;
    }
    __syncthreads();

    // ---------------- Phase 2: gated sum, REVERSE order --------------------
    // Load path identical to round 8 (plain LDG) except iterations it<2
    // (rows 0..7) read the smem stash — branch on compile-time `it`.
    {
        const int g = tid >> 8;          // 0..3 (row group)
        const int r = tid & 255;         // float4 index within the 1024-row
#pragma unroll
        for (int it = (BC_PER_BLK / 4) - 1; it >= 0; it--) {
            int rel = it * 4 + g;
            int bc  = s + rel;

            float w1 = sw1[rel];
            float wa = sw2[0][rel];
            float wb = sw2[1][rel];
            float wc = sw2[2][rel];
            float wd = sw2[3][rel];

            float4 vy, va, vb, vc, vd;
            if (it < 2) {                 // compile-time: rel = it*4+g < 8
                const float4* st = stash4 + rel * 5 * 256;
                vy = st[0 * 256 + r];
                va = st[1 * 256 + r];
                vb = st[2 * 256 + r];
                vc = st[3 * 256 + r];
                vd = st[4 * 256 + r];
            } else {
                size_t base = (size_t)bc * HW;
                vy = ((const float4*)(y  + base))[r];
                va = ((const float4*)(x0 + base))[r];
                vb = ((const float4*)(x1 + base))[r];
                vc = ((const float4*)(x2 + base))[r];
                vd = ((const float4*)(x3 + base))[r];
            }

            float4 res;
            res.x = fmaf(vy.x, w1, fmaf(va.x, wa, fmaf(vb.x, wb, fmaf(vc.x, wc, vd.x * wd))));
            res.y = fmaf(vy.y, w1, fmaf(va.y, wa, fmaf(vb.y, wb, fmaf(vc.y, wc, vd.y * wd))));
            res.z = fmaf(vy.z, w1, fmaf(va.z, wa, fmaf(vb.z, wb, fmaf(vc.z, wc, vd.z * wd))));
            res.w = fmaf(vy.w, w1, fmaf(va.w, wa, fmaf(vb.w, wb, fmaf(vc.w, wc, vd.w * wd))));
            __stcs((float4*)(out + (size_t)bc * HW) + r, res);
        }
    }
}

extern "C" void kernel_launch(void* const* d_in, const int* in_sizes, int n_in,
                              void* d_out, int out_size)
{
    const float* y       = (const float*)d_in[0];
    const float* x0      = (const float*)d_in[1];
    const float* x1      = (const float*)d_in[2];
    const float* x2      = (const float*)d_in[3];
    const float* x3      = (const float*)d_in[4];
    const float* conv1_w = (const float*)d_in[5];
    const float* bn_g    = (const float*)d_in[6];
    const float* bn_b    = (const float*)d_in[7];
    const float* bn_m    = (const float*)d_in[8];
    const float* bn_v    = (const float*)d_in[9];
    const float* conv2_w = (const float*)d_in[10];
    const float* conv2_b = (const float*)d_in[11];
    float* out = (float*)d_out;

    const int dyn_smem = STASKS * 256 * sizeof(float4);   // 163840 B
    cudaFuncSetAttribute(fused_kernel,
                         cudaFuncAttributeMaxDynamicSharedMemorySize, dyn_smem);

    fused_kernel<<<NBLK, 1024, dyn_smem>>>(y, x0, x1, x2, x3,
                                           conv1_w, bn_g, bn_b, bn_m, bn_v,
                                           conv2_w, conv2_b, out);
}